// round 1
// baseline (speedup 1.0000x reference)
#include <cuda_runtime.h>
#include <cstdint>

// Problem constants (from reference):
//   BATCH = 16384, NCONDS = 50, EMB_DIM = 64, table rows = 100002
// Inputs (metadata order):
//   d_in[0]: int32  input       [BATCH, 51]
//   d_in[1]: float  event_table [100002, 64]
// Output: float [BATCH, 3264]  (64 event_emb + 50*64 filtered_cond)

constexpr int EMB      = 64;
constexpr int NCONDS   = 50;
constexpr int ROW_IN   = 1 + NCONDS;          // 51
constexpr int ROW_OUT  = EMB + NCONDS * EMB;  // 3264

__global__ __launch_bounds__(256) void cond_filter_kernel(
    const int*   __restrict__ inp,     // [batch, 51]
    const float* __restrict__ table,   // [100002, 64]
    float*       __restrict__ out,     // [batch, 3264]
    int batch)
{
    const int warp = (blockIdx.x * blockDim.x + threadIdx.x) >> 5;
    const int lane = threadIdx.x & 31;
    if (warp >= batch) return;

    const int* row = inp + (long)warp * ROW_IN;
    float* orow = out + (long)warp * ROW_OUT;

    // ---- event embedding ----
    const int e = __ldg(row);
    const float2 ev = *reinterpret_cast<const float2*>(table + (long)e * EMB + 2 * lane);

    // write un-normalized event embedding
    *reinterpret_cast<float2*>(orow + 2 * lane) = ev;

    // event norm (warp reduction over 64 elements, 2 per lane)
    float ss = ev.x * ev.x + ev.y * ev.y;
    #pragma unroll
    for (int o = 16; o; o >>= 1) ss += __shfl_xor_sync(0xffffffffu, ss, o);
    const float rinv = rsqrtf(ss);
    const float enx = ev.x * rinv;
    const float eny = ev.y * rinv;

    // ---- conditions: filtered_c = cond * dot(event_nrm, cond) / dot(cond, cond) ----
    // Software-pipelined: prefetch next cond's gather before reducing current.
    int    ci = __ldg(row + 1);
    float2 cv = *reinterpret_cast<const float2*>(table + (long)ci * EMB + 2 * lane);

    float* ocond = orow + EMB + 2 * lane;

    #pragma unroll 1
    for (int c = 0; c < NCONDS; ++c) {
        const float2 cur = cv;
        if (c + 1 < NCONDS) {
            ci = __ldg(row + 2 + c);
            cv = *reinterpret_cast<const float2*>(table + (long)ci * EMB + 2 * lane);
        }

        float d_ec = enx * cur.x + eny * cur.y;   // dot(event_nrm, cond)
        float d_cc = cur.x * cur.x + cur.y * cur.y; // dot(cond, cond)
        #pragma unroll
        for (int o = 16; o; o >>= 1) {
            d_ec += __shfl_xor_sync(0xffffffffu, d_ec, o);
            d_cc += __shfl_xor_sync(0xffffffffu, d_cc, o);
        }

        const float s = d_ec / d_cc;
        float2 w;
        w.x = cur.x * s;
        w.y = cur.y * s;
        *reinterpret_cast<float2*>(ocond + (long)c * EMB) = w;
    }
}

extern "C" void kernel_launch(void* const* d_in, const int* in_sizes, int n_in,
                              void* d_out, int out_size)
{
    const int*   inp   = (const int*)d_in[0];
    const float* table = (const float*)d_in[1];
    float*       out   = (float*)d_out;

    const int batch = in_sizes[0] / ROW_IN;   // 16384

    const int threads = 256;                   // 8 warps/block, 1 warp/row
    const int warps_per_block = threads / 32;
    const int blocks = (batch + warps_per_block - 1) / warps_per_block;

    cond_filter_kernel<<<blocks, threads>>>(inp, table, out, batch);
}

// round 2
// speedup vs baseline: 1.4010x; 1.4010x over previous
#include <cuda_runtime.h>
#include <cstdint>

// BATCH=16384, NCONDS=50, EMB=64, table rows=100002
// d_in[0]: int32 input [B,51]   d_in[1]: float table [100002,64]
// out: float [B, 64 + 50*64]

constexpr int EMB     = 64;
constexpr int NCONDS  = 50;
constexpr int ROW_IN  = 1 + NCONDS;           // 51
constexpr int ROW_OUT = EMB + NCONDS * EMB;   // 3264

__global__ __launch_bounds__(256) void cond_filter_kernel(
    const int*   __restrict__ inp,
    const float* __restrict__ table,
    float*       __restrict__ out,
    int batch)
{
    const int warp = (blockIdx.x * blockDim.x + threadIdx.x) >> 5;
    const int lane = threadIdx.x & 31;
    if (warp >= batch) return;

    const int half = lane >> 4;     // 0: even conds, 1: odd conds
    const int hl   = lane & 15;     // lane within 16-lane group (float4 slot)

    const int* row  = inp + (long)warp * ROW_IN;
    float*     orow = out + (long)warp * ROW_OUT;

    // ---- event embedding (both halves load it; need event_nrm in all lanes) ----
    const int e = __ldg(row);
    const float4 ev = *reinterpret_cast<const float4*>(table + (long)e * EMB + 4 * hl);

    if (half == 0)  // write un-normalized event embedding (streaming: no reuse)
        __stcs(reinterpret_cast<float4*>(orow + 4 * hl), ev);

    float ss = ev.x * ev.x + ev.y * ev.y + ev.z * ev.z + ev.w * ev.w;
    #pragma unroll
    for (int o = 8; o; o >>= 1) ss += __shfl_xor_sync(0xffffffffu, ss, o);
    const float rinv = rsqrtf(ss);
    const float enx = ev.x * rinv, eny = ev.y * rinv;
    const float enz = ev.z * rinv, enw = ev.w * rinv;

    // ---- conditions, 2 per iteration (one per 16-lane half) ----
    // filtered_c = cond * dot(event_nrm, cond) / dot(cond, cond)
    int    ci = __ldg(row + 1 + half);
    float4 cv = *reinterpret_cast<const float4*>(table + (long)ci * EMB + 4 * hl);

    float* ocond = orow + EMB + (long)half * EMB + 4 * hl;

    #pragma unroll 1
    for (int c = 0; c < NCONDS; c += 2) {
        const float4 cur = cv;
        if (c + 2 < NCONDS) {  // prefetch next pair
            ci = __ldg(row + 3 + c + half);
            cv = *reinterpret_cast<const float4*>(table + (long)ci * EMB + 4 * hl);
        }

        float dec = enx * cur.x + eny * cur.y + enz * cur.z + enw * cur.w;
        float dcc = cur.x * cur.x + cur.y * cur.y + cur.z * cur.z + cur.w * cur.w;
        #pragma unroll
        for (int o = 8; o; o >>= 1) {   // reduce within each 16-lane half
            dec += __shfl_xor_sync(0xffffffffu, dec, o);
            dcc += __shfl_xor_sync(0xffffffffu, dcc, o);
        }

        const float s = dec / dcc;
        float4 w;
        w.x = cur.x * s; w.y = cur.y * s; w.z = cur.z * s; w.w = cur.w * s;
        __stcs(reinterpret_cast<float4*>(ocond + (long)c * EMB), w);
    }
}

extern "C" void kernel_launch(void* const* d_in, const int* in_sizes, int n_in,
                              void* d_out, int out_size)
{
    const int*   inp   = (const int*)d_in[0];
    const float* table = (const float*)d_in[1];
    float*       out   = (float*)d_out;

    const int batch = in_sizes[0] / ROW_IN;

    const int threads = 256;                  // 8 warps/block, 1 warp/row
    const int blocks  = (batch + 7) / 8;

    cond_filter_kernel<<<blocks, threads>>>(inp, table, out, batch);
}